// round 17
// baseline (speedup 1.0000x reference)
#include <cuda_runtime.h>
#include <cuda_bf16.h>
#include <math.h>
#include <stdint.h>

// ---------------------------------------------------------------------------
// Problem constants
// ---------------------------------------------------------------------------
#define B_   8
#define C_   256
#define S_   1024
#define H_   8
#define D_   64
#define HID_ 512
#define O1_  1536

__device__ float    g_qkv[B_ * O1_ * S_];        // [b][o][s] fp32
__device__ float    g_sin[S_ * 16];
__device__ float    g_cos[S_ * 16];
// pre-split bf16 pair-packed operands (word = bf16x2 of k-pair)
__device__ uint32_t g_wqh[128 * O1_], g_wql[128 * O1_];   // w_qkv^T  [kp][o]
__device__ uint32_t g_woh[256 * C_],  g_wol[256 * C_];    // w_out^T  [kp][o]
__device__ uint32_t g_xh[B_ * 128 * S_], g_xl[B_ * 128 * S_];   // x   [b][kp][s]
__device__ uint32_t g_oh[B_ * 256 * S_], g_ol[B_ * 256 * S_];   // att [b][kp][s]

// ---------------------------------------------------------------------------
// MMA + pack helpers
// ---------------------------------------------------------------------------
__device__ __forceinline__ void mma_tf32(float c[4],
    uint32_t a0, uint32_t a1, uint32_t a2, uint32_t a3,
    uint32_t b0, uint32_t b1)
{
    asm volatile(
        "mma.sync.aligned.m16n8k8.row.col.f32.tf32.tf32.f32 "
        "{%0,%1,%2,%3}, {%4,%5,%6,%7}, {%8,%9}, {%0,%1,%2,%3};"
        : "+f"(c[0]), "+f"(c[1]), "+f"(c[2]), "+f"(c[3])
        : "r"(a0), "r"(a1), "r"(a2), "r"(a3), "r"(b0), "r"(b1));
}

__device__ __forceinline__ void mma_bf16(float c[4],
    uint32_t a0, uint32_t a1, uint32_t a2, uint32_t a3,
    uint32_t b0, uint32_t b1)
{
    asm volatile(
        "mma.sync.aligned.m16n8k16.row.col.f32.bf16.bf16.f32 "
        "{%0,%1,%2,%3}, {%4,%5,%6,%7}, {%8,%9}, {%0,%1,%2,%3};"
        : "+f"(c[0]), "+f"(c[1]), "+f"(c[2]), "+f"(c[3])
        : "r"(a0), "r"(a1), "r"(a2), "r"(a3), "r"(b0), "r"(b1));
}

__device__ __forceinline__ void split_pack_bf16(float v0, float v1,
                                                uint32_t& hp, uint32_t& lp)
{
    __nv_bfloat16 h0 = __float2bfloat16_rn(v0);
    __nv_bfloat16 h1 = __float2bfloat16_rn(v1);
    __nv_bfloat16 l0 = __float2bfloat16_rn(v0 - __bfloat162float(h0));
    __nv_bfloat16 l1 = __float2bfloat16_rn(v1 - __bfloat162float(h1));
    __nv_bfloat162 hv = __halves2bfloat162(h0, h1);
    __nv_bfloat162 lv = __halves2bfloat162(l0, l1);
    hp = *(uint32_t*)&hv;
    lp = *(uint32_t*)&lv;
}

__device__ __forceinline__ void cp_async16(uint32_t s, const void* g) {
    asm volatile("cp.async.cg.shared.global [%0], [%1], 16;" :: "r"(s), "l"(g));
}
#define CP_COMMIT() asm volatile("cp.async.commit_group;")
#define CP_WAIT1()  asm volatile("cp.async.wait_group 1;")
#define CP_WAIT0()  asm volatile("cp.async.wait_group 0;")

// ---------------------------------------------------------------------------
// 0) fused prep: sin/cos table + weight splits + x split, dispatched by block
// ---------------------------------------------------------------------------
__global__ __launch_bounds__(256) void prep_kernel(
    const float* __restrict__ x,
    const float* __restrict__ w_qkv,
    const float* __restrict__ w_out)
{
    int blk = blockIdx.x;
    int tid = threadIdx.x;

    if (blk < 64) {                              // sin/cos (16384 entries)
        int id = blk * 256 + tid;
        int s = id >> 4;
        int j = id & 15;
        float invf = (float)pow(10000.0, -(double)j / 16.0);
        double ang = (double)s * (double)invf;
        g_sin[id] = (float)sin(ang);
        g_cos[id] = (float)cos(ang);
    } else if (blk < 832) {                      // w_qkv split: 128*1536
        int id = (blk - 64) * 256 + tid;
        int kp = id / O1_, o = id - kp * O1_;
        uint32_t hp, lp;
        split_pack_bf16(w_qkv[(size_t)o * 256 + 2 * kp],
                        w_qkv[(size_t)o * 256 + 2 * kp + 1], hp, lp);
        g_wqh[id] = hp; g_wql[id] = lp;
    } else if (blk < 1088) {                     // w_out split: 256*256
        int id = (blk - 832) * 256 + tid;
        int kp = id / C_, o = id - kp * C_;
        uint32_t hp, lp;
        split_pack_bf16(w_out[(size_t)o * 512 + 2 * kp],
                        w_out[(size_t)o * 512 + 2 * kp + 1], hp, lp);
        g_woh[id] = hp; g_wol[id] = lp;
    } else {                                     // x split
        int id = (blk - 1088) * 256 + tid;
        int s4 = (id & 255) * 4;
        int kp = (id >> 8) & 127;
        int b  = id >> 15;
        float4 v0 = *(const float4*)(x + ((size_t)b * 256 + 2 * kp) * S_ + s4);
        float4 v1 = *(const float4*)(x + ((size_t)b * 256 + 2 * kp + 1) * S_ + s4);
        uint32_t h0, l0, h1, l1, h2, l2, h3, l3;
        split_pack_bf16(v0.x, v1.x, h0, l0);
        split_pack_bf16(v0.y, v1.y, h1, l1);
        split_pack_bf16(v0.z, v1.z, h2, l2);
        split_pack_bf16(v0.w, v1.w, h3, l3);
        size_t oidx = ((size_t)b * 128 + kp) * S_ + s4;
        *(uint4*)(g_xh + oidx) = make_uint4(h0, h1, h2, h3);
        *(uint4*)(g_xl + oidx) = make_uint4(l0, l1, l2, l3);
    }
}

// ---------------------------------------------------------------------------
// 1+4) bf16 3-term GEMM on PRE-SPLIT operands.
//      3-stage cp.async pipeline, ONE __syncthreads per k-chunk.
//      stage layout (uint32 words): Ah +0 (576), Al +576, Bh +1152 (1088),
//      Bl +2240  -> 3328 words/stage, 3 stages = 9984 words (40 KB).
// ---------------------------------------------------------------------------
#define G_STAGE 3328
#define G_SMEM_WORDS (3 * G_STAGE)

template<int KDIM, bool BIAS, bool ROPE>
__global__ __launch_bounds__(256) void gemm_pre_kernel(
    const uint32_t* __restrict__ Wh, const uint32_t* __restrict__ Wl,
    const uint32_t* __restrict__ Xh, const uint32_t* __restrict__ Xl,
    const float* __restrict__ bias, float* __restrict__ C, int Mtot)
{
    constexpr int KP = KDIM / 2;
    constexpr int NC = KDIM / 16;

    __shared__ uint32_t smg[G_SMEM_WORDS];

    const int tid  = threadIdx.x;
    const int lane = tid & 31, warp = tid >> 5;
    const int g = lane >> 2, tg = lane & 3;
    const int wm = warp & 1, wn = warp >> 1;
    const int mbase = wm * 32, nbase = wn * 32;

    const int s0 = blockIdx.x * 128;
    const int o0 = blockIdx.y * 64;
    const int b  = blockIdx.z;

    uint32_t smbase = (uint32_t)__cvta_generic_to_shared(smg);

    const int ar = (tid & 127) >> 4;
    const int aq = tid & 15;
    const bool alo = tid >= 128;
    const int br = tid >> 5;
    const int bq = tid & 31;

    const uint32_t* Wsrc = alo ? Wl : Wh;
    const uint32_t* XhB = Xh + (size_t)b * KP * S_ + s0;
    const uint32_t* XlB = Xl + (size_t)b * KP * S_ + s0;

    auto issue = [&](int chunk, int slot) {
        int kp0 = chunk * 8;
        uint32_t base = slot * G_STAGE;
        uint32_t aoff = base + (alo ? 576 : 0);
        cp_async16(smbase + (aoff + ar * 72 + aq * 4) * 4,
                   Wsrc + (size_t)(kp0 + ar) * Mtot + o0 + aq * 4);
        cp_async16(smbase + (base + 1152 + br * 136 + bq * 4) * 4,
                   XhB + (size_t)(kp0 + br) * S_ + bq * 4);
        cp_async16(smbase + (base + 2240 + br * 136 + bq * 4) * 4,
                   XlB + (size_t)(kp0 + br) * S_ + bq * 4);
    };

    // prologue: stages 0,1 in flight
    issue(0, 0); CP_COMMIT();
    issue(1, 1); CP_COMMIT();

    float acc[2][4][4] = {};

    for (int c = 0; c < NC; c++) {
        CP_WAIT1();        // chunk c has landed (c+1 may still be in flight)
        __syncthreads();   // chunk c visible; all warps done with chunk c-1
        if (c + 2 < NC) issue(c + 2, (c + 2) % 3);   // overwrites slot of c-1
        CP_COMMIT();       // commit every iter (possibly empty) for counting

        const uint32_t* St  = smg + (c % 3) * G_STAGE;
        const uint32_t* AhP = St;
        const uint32_t* AlP = St + 576;
        const uint32_t* BhP = St + 1152;
        const uint32_t* BlP = St + 2240;

        uint32_t ah[2][4], al[2][4];
#pragma unroll
        for (int mt = 0; mt < 2; mt++) {
            int r = mbase + mt * 16 + g;
            ah[mt][0] = AhP[tg * 72 + r];
            ah[mt][1] = AhP[tg * 72 + r + 8];
            ah[mt][2] = AhP[(tg + 4) * 72 + r];
            ah[mt][3] = AhP[(tg + 4) * 72 + r + 8];
            al[mt][0] = AlP[tg * 72 + r];
            al[mt][1] = AlP[tg * 72 + r + 8];
            al[mt][2] = AlP[(tg + 4) * 72 + r];
            al[mt][3] = AlP[(tg + 4) * 72 + r + 8];
        }
        uint32_t bh[4][2], bl[4][2];
#pragma unroll
        for (int nt = 0; nt < 4; nt++) {
            int n = nbase + nt * 8 + g;
            bh[nt][0] = BhP[tg * 136 + n];
            bh[nt][1] = BhP[(tg + 4) * 136 + n];
            bl[nt][0] = BlP[tg * 136 + n];
            bl[nt][1] = BlP[(tg + 4) * 136 + n];
        }
#pragma unroll
        for (int mt = 0; mt < 2; mt++)
#pragma unroll
            for (int nt = 0; nt < 4; nt++) {
                mma_bf16(acc[mt][nt], ah[mt][0], ah[mt][1], ah[mt][2], ah[mt][3], bh[nt][0], bh[nt][1]);
                mma_bf16(acc[mt][nt], ah[mt][0], ah[mt][1], ah[mt][2], ah[mt][3], bl[nt][0], bl[nt][1]);
                mma_bf16(acc[mt][nt], al[mt][0], al[mt][1], al[mt][2], al[mt][3], bh[nt][0], bh[nt][1]);
            }
    }

    if (ROPE && o0 < 2 * HID_ && wm == 0) {
#pragma unroll
        for (int rh = 0; rh < 2; rh++) {
            int d = rh * 8 + g;
#pragma unroll
            for (int nt = 0; nt < 4; nt++)
#pragma unroll
                for (int cl = 0; cl < 2; cl++) {
                    int col = s0 + nbase + nt * 8 + tg * 2 + cl;
                    float cs = g_cos[col * 16 + d];
                    float sn = g_sin[col * 16 + d];
                    float x = acc[0][nt][rh * 2 + cl];
                    float y = acc[1][nt][rh * 2 + cl];
                    acc[0][nt][rh * 2 + cl] = x * cs - y * sn;
                    acc[1][nt][rh * 2 + cl] = y * cs + x * sn;
                }
        }
    }

    float* Cp = C + ((size_t)b * Mtot + o0) * S_ + s0;
#pragma unroll
    for (int mt = 0; mt < 2; mt++)
#pragma unroll
        for (int rh = 0; rh < 2; rh++) {
            int row = mbase + mt * 16 + rh * 8 + g;
            float bv = BIAS ? bias[o0 + row] : 0.f;
#pragma unroll
            for (int nt = 0; nt < 4; nt++) {
                int col = nbase + nt * 8 + tg * 2;
                float2 v2 = make_float2(acc[mt][nt][rh * 2 + 0] + bv,
                                        acc[mt][nt][rh * 2 + 1] + bv);
                *(float2*)(Cp + (size_t)row * S_ + col) = v2;
            }
        }
}

// ---------------------------------------------------------------------------
// 2b) L2 norm over the sequence axis (in-place on fp32 qkv)
// ---------------------------------------------------------------------------
__global__ __launch_bounds__(256) void l2norm_kernel(float* __restrict__ qkv)
{
    int row = blockIdx.x;
    int b = row >> 10;
    int o = row & 1023;
    float* p = qkv + ((size_t)b * O1_ + o) * S_;

    int tid = threadIdx.x;
    float4 v = *(float4*)(p + tid * 4);
    float ss = v.x * v.x + v.y * v.y + v.z * v.z + v.w * v.w;
#pragma unroll
    for (int off = 16; off; off >>= 1)
        ss += __shfl_xor_sync(0xffffffffu, ss, off);

    __shared__ float wss[8];
    if ((tid & 31) == 0) wss[tid >> 5] = ss;
    __syncthreads();
    if (tid < 32) {
        float t = (tid < 8) ? wss[tid] : 0.f;
#pragma unroll
        for (int off = 4; off; off >>= 1)
            t += __shfl_xor_sync(0xffffffffu, t, off);
        if (tid == 0) wss[0] = t;
    }
    __syncthreads();

    float inv = 1.0f / fmaxf(sqrtf(wss[0]), 1e-12f);
    v.x *= inv; v.y *= inv; v.z *= inv; v.w *= inv;
    *(float4*)(p + tid * 4) = v;
}

// ---------------------------------------------------------------------------
// 3) Attention (R16 config, unchanged — best known at 124.4 us):
//    2 blocks/SM, double-buffered cp.async K/V (j-tile 64), fragment-major Q,
//    register-resident P, staged O reduction, bf16 hi/lo packed output.
// ---------------------------------------------------------------------------
#define AT_QS 0            // 64*72 = 4608 (reused as Ot stride 68 in epilogue)
#define AT_K0 4608
#define AT_K1 9216
#define AT_V0 13824        // 64*68 = 4352
#define AT_V1 18176
#define AT_L  22528        // 64
#define AT_QF 22592        // 2*8*2*128 = 4096 fragment-major Q
#define AT_SMEM_FLOATS 26688   // 106.8 KB

__global__ __launch_bounds__(256, 2) void attn_tc_kernel(
    const float* __restrict__ qkv,
    uint32_t* __restrict__ Oh, uint32_t* __restrict__ Ol)
{
    extern __shared__ float sm[];
    float* Qs  = sm + AT_QS;
    float* Lsm = sm + AT_L;
    float* Qf  = sm + AT_QF;

    const int tid  = threadIdx.x;
    const int lane = tid & 31;
    const int warp = tid >> 5;
    const int g  = lane >> 2;
    const int tg = lane & 3;
    const int wi = warp & 1;
    const int wq = warp >> 1;          // 0..3: 16-j slice
    const int ib = wi * 32;
    const int jh = wq * 16;
    const int fg = (g >> 1) | ((g & 1) << 2);   // K column permutation

    const int i0 = blockIdx.x * 64;
    const int h  = blockIdx.y;
    const int b  = blockIdx.z;

    const float* Qg = qkv + ((size_t)b * O1_ + h * D_) * S_;
    const float* Kg = Qg + (size_t)HID_ * S_;
    const float* Vg = Qg + (size_t)(2 * HID_) * S_;

    uint32_t smbase = (uint32_t)__cvta_generic_to_shared(sm);

    // Q tile [d][i], stride 72
    for (int v = tid; v < 1024; v += 256) {
        int d = v >> 4, iq = v & 15;
        *(float4*)&Qs[d * 72 + iq * 4] =
            *(const float4*)(Qg + (size_t)d * S_ + i0 + iq * 4);
    }
    if (tid < 64) Lsm[tid] = 0.f;

    const int ldd = tid >> 4, ljq = tid & 15;
    auto issue_kv = [&](int buf, int j0) {
        uint32_t koff = (buf ? AT_K1 : AT_K0);
        uint32_t voff = (buf ? AT_V1 : AT_V0);
#pragma unroll
        for (int r = 0; r < 4; r++) {
            int d = ldd + r * 16;
            cp_async16(smbase + (koff + d * 72 + ljq * 4) * 4,
                       Kg + (size_t)d * S_ + j0 + ljq * 4);
            cp_async16(smbase + (voff + d * 68 + ljq * 4) * 4,
                       Vg + (size_t)d * S_ + j0 + ljq * 4);
        }
    };

    issue_kv(0, 0);
    CP_COMMIT();
    __syncthreads();   // Qs complete before fragment build

    // Build fragment-major Q: warps wq==0 (one per i-half) write their frags.
    if (wq == 0) {
#pragma unroll
        for (int kk = 0; kk < 8; kk++) {
            const int k0 = kk * 8;
#pragma unroll
            for (int mt = 0; mt < 2; mt++) {
                int r = ib + mt * 16 + g;
                float4 qa;
                qa.x = Qs[(k0 + tg) * 72 + r];
                qa.y = Qs[(k0 + tg) * 72 + r + 8];
                qa.z = Qs[(k0 + tg + 4) * 72 + r];
                qa.w = Qs[(k0 + tg + 4) * 72 + r + 8];
                *(float4*)&Qf[(((wi * 8) + kk) * 2 + mt) * 128 + lane * 4] = qa;
            }
        }
    }
    __syncthreads();

    float oacc[2][8][4] = {};
    float l_acc[2][2]   = {};

    for (int it = 0; it < 16; it++) {
        const int cur = it & 1;
        __syncthreads();
        if (it + 1 < 16) {
            issue_kv(cur ^ 1, (it + 1) * 64);
            CP_COMMIT();
            CP_WAIT1();
        } else {
            CP_WAIT0();
        }
        __syncthreads();

        const float* Ks = sm + (cur ? AT_K1 : AT_K0);
        const float* Vs = sm + (cur ? AT_V1 : AT_V0);

        // ---- S phase: S[32 i][16 j]; A-fragments via one float4 LDS each
        float sacc[2][2][4] = {};
#pragma unroll
        for (int kk = 0; kk < 8; kk++) {
            const int k0 = kk * 8;
            uint4 a[2];
#pragma unroll
            for (int mt = 0; mt < 2; mt++)
                a[mt] = *(uint4*)&Qf[(((wi * 8) + kk) * 2 + mt) * 128 + lane * 4];
            uint32_t bb[2][2];
#pragma unroll
            for (int nt = 0; nt < 2; nt++) {
                int jc = jh + nt * 8 + fg;
                bb[nt][0] = __float_as_uint(Ks[(k0 + tg) * 72 + jc]);
                bb[nt][1] = __float_as_uint(Ks[(k0 + tg + 4) * 72 + jc]);
            }
#pragma unroll
            for (int mt = 0; mt < 2; mt++)
#pragma unroll
                for (int nt = 0; nt < 2; nt++)
                    mma_tf32(sacc[mt][nt], a[mt].x, a[mt].y, a[mt].z, a[mt].w,
                             bb[nt][0], bb[nt][1]);
        }

        // ---- exp in place + row sums
#pragma unroll
        for (int mt = 0; mt < 2; mt++)
#pragma unroll
            for (int nt = 0; nt < 2; nt++) {
                float p0 = __expf(10.f * sacc[mt][nt][0]);
                float p1 = __expf(10.f * sacc[mt][nt][1]);
                float p2 = __expf(10.f * sacc[mt][nt][2]);
                float p3 = __expf(10.f * sacc[mt][nt][3]);
                sacc[mt][nt][0] = p0; sacc[mt][nt][1] = p1;
                sacc[mt][nt][2] = p2; sacc[mt][nt][3] = p3;
                l_acc[mt][0] += p0 + p1;
                l_acc[mt][1] += p2 + p3;
            }

        // ---- O phase: P (registers) x V^T, n = all 64 d, k = 16 j
#pragma unroll
        for (int ks = 0; ks < 2; ks++) {
            const int jk = jh + ks * 8;
            uint32_t bb[8][2];
#pragma unroll
            for (int nt = 0; nt < 8; nt++) {
                int dc = nt * 8 + g;
                bb[nt][0] = __float_as_uint(Vs[dc * 68 + jk + tg]);
                bb[nt][1] = __float_as_uint(Vs[dc * 68 + jk + tg + 4]);
            }
#pragma unroll
            for (int mt = 0; mt < 2; mt++) {
                uint32_t a0 = __float_as_uint(sacc[mt][ks][0]);
                uint32_t a1 = __float_as_uint(sacc[mt][ks][2]);
                uint32_t a2 = __float_as_uint(sacc[mt][ks][1]);
                uint32_t a3 = __float_as_uint(sacc[mt][ks][3]);
#pragma unroll
                for (int nt = 0; nt < 8; nt++)
                    mma_tf32(oacc[mt][nt], a0, a1, a2, a3, bb[nt][0], bb[nt][1]);
            }
        }
    }

    // ---- row sums: reduce over tg lanes, merge 4 j-warps via atomicAdd
#pragma unroll
    for (int mt = 0; mt < 2; mt++)
#pragma unroll
        for (int rh = 0; rh < 2; rh++) {
            float l = l_acc[mt][rh];
            l += __shfl_xor_sync(0xffffffffu, l, 1);
            l += __shfl_xor_sync(0xffffffffu, l, 2);
            if (tg == 0)
                atomicAdd(&Lsm[ib + mt * 16 + rh * 8 + g], l);
        }
    __syncthreads();

    // ---- staged reduction of partial O across 4 j-warps into Ot=Qs (str 68)
#pragma unroll
    for (int r = 0; r < 4; r++) {
        if (wq == r) {
#pragma unroll
            for (int mt = 0; mt < 2; mt++)
#pragma unroll
                for (int nt = 0; nt < 8; nt++)
#pragma unroll
                    for (int c = 0; c < 4; c++) {
                        int row = ib + mt * 16 + g + ((c >> 1) << 3);
                        int col = nt * 8 + tg * 2 + (c & 1);
                        if (r == 0) Qs[col * 68 + row] = oacc[mt][nt][c];
                        else        Qs[col * 68 + row] += oacc[mt][nt][c];
                    }
        }
        __syncthreads();
    }

    if (tid < 64) Lsm[tid] = 1.0f / Lsm[tid];
    __syncthreads();

    // ---- normalized store as packed bf16 hi/lo d-pairs: O[b][kp][s]
    for (int v = tid; v < 512; v += 256) {
        int p = v >> 4, iq = v & 15;
        float4 o0 = *(float4*)&Qs[(2 * p) * 68 + iq * 4];
        float4 o1 = *(float4*)&Qs[(2 * p + 1) * 68 + iq * 4];
        float i0s = Lsm[iq * 4 + 0], i1s = Lsm[iq * 4 + 1];
        float i2s = Lsm[iq * 4 + 2], i3s = Lsm[iq * 4 + 3];
        o0.x *= i0s; o0.y *= i1s; o0.z *= i2s; o0.w *= i3s;
        o1.x *= i0s; o1.y *= i1s; o1.z *= i2s; o1.w *= i3s;
        uint32_t h0, l0, h1, l1, h2, l2, h3, l3;
        split_pack_bf16(o0.x, o1.x, h0, l0);
        split_pack_bf16(o0.y, o1.y, h1, l1);
        split_pack_bf16(o0.z, o1.z, h2, l2);
        split_pack_bf16(o0.w, o1.w, h3, l3);
        size_t oidx = ((size_t)b * 256 + h * 32 + p) * S_ + i0 + iq * 4;
        *(uint4*)(Oh + oidx) = make_uint4(h0, h1, h2, h3);
        *(uint4*)(Ol + oidx) = make_uint4(l0, l1, l2, l3);
    }
}

// ---------------------------------------------------------------------------
// Launch
// ---------------------------------------------------------------------------
extern "C" void kernel_launch(void* const* d_in, const int* in_sizes, int n_in,
                              void* d_out, int out_size)
{
    const float* x     = (const float*)d_in[0];
    const float* w_qkv = (const float*)d_in[1];
    const float* w_out = (const float*)d_in[2];
    const float* b_out = (const float*)d_in[3];
    float* out = (float*)d_out;

    float* qkv;   cudaGetSymbolAddress((void**)&qkv, g_qkv);
    uint32_t *wqh, *wql, *woh, *wol, *xh, *xl, *oh, *ol;
    cudaGetSymbolAddress((void**)&wqh, g_wqh);
    cudaGetSymbolAddress((void**)&wql, g_wql);
    cudaGetSymbolAddress((void**)&woh, g_woh);
    cudaGetSymbolAddress((void**)&wol, g_wol);
    cudaGetSymbolAddress((void**)&xh, g_xh);
    cudaGetSymbolAddress((void**)&xl, g_xl);
    cudaGetSymbolAddress((void**)&oh, g_oh);
    cudaGetSymbolAddress((void**)&ol, g_ol);

    static const size_t attn_smem = AT_SMEM_FLOATS * sizeof(float);  // ~107 KB
    cudaFuncSetAttribute(attn_tc_kernel,
                         cudaFuncAttributeMaxDynamicSharedMemorySize,
                         (int)attn_smem);

    // fused prep: sin/cos + weight splits + x split (one launch)
    prep_kernel<<<2112, 256>>>(x, w_qkv, w_out);

    {   // QKV projection (pre-split bf16x3, 3-stage pipeline, fused RoPE)
        dim3 grid(S_ / 128, O1_ / 64, B_);
        gemm_pre_kernel<256, false, true><<<grid, 256>>>(wqh, wql, xh, xl,
                                                         nullptr, qkv, O1_);
    }

    l2norm_kernel<<<B_ * 2 * HID_, 256>>>(qkv);

    {   // Attention (fragment-major Q, 2 blocks/SM, double-buffered K/V)
        dim3 grid(S_ / 64, H_, B_);
        attn_tc_kernel<<<grid, 256, attn_smem>>>(qkv, oh, ol);
    }

    {   // Output projection (pre-split bf16x3, 3-stage pipeline + bias)
        dim3 grid(S_ / 128, C_ / 64, B_);
        gemm_pre_kernel<512, true, false><<<grid, 256>>>(woh, wol, oh, ol,
                                                         b_out, out, C_);
    }
}